// round 4
// baseline (speedup 1.0000x reference)
#include <cuda_runtime.h>
#include <cuda_bf16.h>
#include <math.h>

// Problem constants (fixed by the dataset)
#define B_   2
#define C_   64
#define E_   4
#define HLR_ 192
#define WLR_ 192
#define HHR_ 384
#define WHR_ 384

// Precomputed per-parity quantities (4 variants: hp*2+wp)
__device__ float g_wc[2][2][8][64];    // dynamic compress weights [hp][wp][j][c]
__device__ float g_we[2][2][64][8];    // dynamic expand weights   [hp][wp][c][j]
__device__ int   g_dx[2][2];           // floor of x sample offset (per class)
__device__ int   g_dy[2][2];           // floor of y sample offset
__device__ float g_wx[2][2];           // frac x
__device__ float g_wy[2][2];           // frac y

// ---------------------------------------------------------------------------
// Kernel 0: compute the 4 parity variants of the MLP outputs, the
// routing-mixed dynamic weights, and the separable-sample constants.
// ---------------------------------------------------------------------------
__global__ void __launch_bounds__(256) precompute_kernel(
    const float* __restrict__ w1, const float* __restrict__ b1,
    const float* __restrict__ w2, const float* __restrict__ b2,
    const float* __restrict__ rw, const float* __restrict__ rb,
    const float* __restrict__ ow, const float* __restrict__ ob,
    const float* __restrict__ WC, const float* __restrict__ WE)
{
    __shared__ float s_emb[4][64];
    __shared__ float s_rt[4][4];
    __shared__ float s_off[4][2];

    int tid = threadIdx.x;
    int v = tid >> 6;        // variant 0..3
    int o = tid & 63;        // output neuron
    int hp = v >> 1, wp = v & 1;

    float ch = (hp + 0.5f) * 0.5f; ch = ch - floorf(ch + 0.001f) - 0.5f;
    float cw = (wp + 0.5f) * 0.5f; cw = cw - floorf(cw + 0.001f) - 0.5f;
    float inp0 = 0.5f, inp1 = 0.5f, inp2 = ch, inp3 = cw;

    float acc = b2[o];
    #pragma unroll 8
    for (int k = 0; k < 64; k++) {
        float e1 = b1[k]
                 + w1[k*4+0]*inp0 + w1[k*4+1]*inp1
                 + w1[k*4+2]*inp2 + w1[k*4+3]*inp3;
        e1 = fmaxf(e1, 0.0f);
        acc += w2[o*64 + k] * e1;
    }
    acc = fmaxf(acc, 0.0f);
    s_emb[v][o] = acc;
    __syncthreads();

    if (o < E_) {
        float a = rb[o];
        for (int k = 0; k < 64; k++) a += rw[o*64 + k] * s_emb[v][k];
        s_rt[v][o] = 1.0f / (1.0f + expf(-a));
    }
    if (o >= 8 && o < 10) {
        int k = o - 8;
        float a = ob[k];
        for (int j = 0; j < 64; j++) a += ow[k*64 + j] * s_emb[v][j];
        s_off[v][k] = a;
    }
    __syncthreads();

    // derived separable-sampling constants (one thread per variant)
    if (o == 0) {
        float offx = s_off[v][0];
        float offy = s_off[v][1];
        float tx = (wp + 0.5f) * 0.5f - 0.5f + offx;
        float ty = (hp + 0.5f) * 0.5f - 0.5f + offy;
        float fx = floorf(tx), fy = floorf(ty);
        g_dx[hp][wp] = (int)fx;  g_wx[hp][wp] = tx - fx;
        g_dy[hp][wp] = (int)fy;  g_wy[hp][wp] = ty - fy;
    }

    // dynamic weights: 4 variants x 512 values each for wc and we
    float* gwc = &g_wc[0][0][0][0];
    float* gwe = &g_we[0][0][0][0];
    for (int idx = tid; idx < 4*512; idx += 256) {
        int vv = idx >> 9;
        int r  = idx & 511;
        float ac = 0.0f, ae = 0.0f;
        #pragma unroll
        for (int e = 0; e < E_; e++) {
            float rt = s_rt[vv][e];
            ac += rt * WC[e*512 + r];
            ae += rt * WE[e*512 + r];
        }
        gwc[vv*512 + r] = ac;
        gwe[vv*512 + r] = ae;
    }
}

// ---------------------------------------------------------------------------
// Main kernel.
// Block: 512 threads = 16 warps; warp ww: q = ww&1 (w-parity), g = ww>>1.
// Block tile: 2 HR rows (h = 2*by+hp) x 128 HR cols (w = 2*(bx*64+m)+q), 64 ch.
// Per hp phase:
//   stage  vb[q][c][col] = (1-wy)*LR(y0) + wy*LR(y0+1)   (zero-filled OOB)
//   taps   fea = (1-wx)*vb[m] + wx*vb[m+1]               (2 LDS per elem)
//   mid    two-phase smem reduction over channel groups
//   out    expand + residual, store
// ---------------------------------------------------------------------------
#define VB_STRIDE 66
#define VB_Q      (64 * VB_STRIDE)           // 4224 floats per parity
#define PART_OFF  (2 * VB_Q)                 // 8448
#define MIDF_OFF  (PART_OFF + 8 * 8 * 128)   // 16640
#define SMEM_FLTS (MIDF_OFF + 8 * 128)       // 17664
#define SMEM_BYTES (SMEM_FLTS * 4)           // 70656

__global__ void __launch_bounds__(512, 3) upsample_main(
    const float* __restrict__ fused, float* __restrict__ out)
{
    extern __shared__ float sm[];
    float* part = sm + PART_OFF;   // [j][g][px]  8*8*128
    float* midf = sm + MIDF_OFF;   // [j][px]     8*128

    const int tid = threadIdx.x;
    const int l  = tid & 31;
    const int ww = tid >> 5;
    const int q  = ww & 1;
    const int g  = ww >> 1;
    const int bx = blockIdx.x;      // 0..2   (128 HR cols each)
    const int by = blockIdx.y;      // 0..191 (HR row pair)
    const int b  = blockIdx.z;

    const int mbase = bx * 64;      // LR-space column base (64 m values)

    #pragma unroll
    for (int hp = 0; hp < 2; hp++) {
        // ---- Stage vb: vertical interp of LR rows, zero-padded -----------
        {
            const int dy0 = g_dy[hp][0], dy1v = g_dy[hp][1];
            const int dx0 = g_dx[hp][0], dx1v = g_dx[hp][1];
            const float wyA = g_wy[hp][0], wyB = g_wy[hp][1];
            const int N = 2 * 64 * 65;                // 8320 entries
            for (int idx = tid; idx < N; idx += 512) {
                int qq = idx >= 4160;
                int r  = idx - qq * 4160;
                int c  = r / 65;
                int mm = r - c * 65;
                int yA = by + (qq ? dy1v : dy0);
                int xg = mbase + (qq ? dx1v : dx0) + mm;
                float wy1 = qq ? wyB : wyA;
                float wy0 = 1.0f - wy1;
                bool xin = (xg >= 0) && (xg < WLR_);
                const float* basep = fused + (size_t)(b * C_ + c) * (HLR_ * WLR_);
                float v0 = (xin && yA >= 0   && yA < HLR_)     ? __ldg(basep + yA * WLR_ + xg)       : 0.0f;
                float v1 = (xin && yA + 1 >= 0 && yA + 1 < HLR_) ? __ldg(basep + (yA + 1) * WLR_ + xg) : 0.0f;
                sm[qq * VB_Q + c * VB_STRIDE + mm] = wy0 * v0 + wy1 * v1;
            }
        }
        __syncthreads();

        // ---- Taps + compress (weights register-resident, warp-uniform) ---
        float fea[2][8];
        {
            const float4* wc4 = ((const float4*)&g_wc[hp][q][0][0]) + g * 2; // row stride 16 f4
            float4 wa[8], wb[8];
            #pragma unroll
            for (int j = 0; j < 8; j++) { wa[j] = wc4[j * 16]; wb[j] = wc4[j * 16 + 1]; }
            const float wx1 = g_wx[hp][q], wx0 = 1.0f - wx1;

            #pragma unroll
            for (int t = 0; t < 2; t++) {
                const int ml = l + t * 32;
                const float* vrow = sm + q * VB_Q + (g * 8) * VB_STRIDE;
                #pragma unroll
                for (int i = 0; i < 8; i++) {
                    const float* vr = vrow + i * VB_STRIDE;
                    fea[t][i] = wx0 * vr[ml] + wx1 * vr[ml + 1];
                }
                const int px = q * 64 + ml;
                float4 fa = make_float4(fea[t][0], fea[t][1], fea[t][2], fea[t][3]);
                float4 fb = make_float4(fea[t][4], fea[t][5], fea[t][6], fea[t][7]);
                #pragma unroll
                for (int j = 0; j < 8; j++) {
                    float a = wa[j].x * fa.x + wa[j].y * fa.y + wa[j].z * fa.z + wa[j].w * fa.w
                            + wb[j].x * fb.x + wb[j].y * fb.y + wb[j].z * fb.z + wb[j].w * fb.w;
                    part[(j * 8 + g) * 128 + px] = a;
                }
            }
        }
        __syncthreads();

        // ---- Reduce partials over channel groups -------------------------
        {
            const int j = ww >> 1, half = ww & 1;
            #pragma unroll
            for (int t2 = 0; t2 < 2; t2++) {
                const int px = half * 64 + t2 * 32 + l;
                float s = 0.0f;
                #pragma unroll
                for (int gg = 0; gg < 8; gg++) s += part[(j * 8 + gg) * 128 + px];
                midf[j * 128 + px] = s;
            }
        }
        __syncthreads();

        // ---- Expand + residual + store ------------------------------------
        {
            const float4* we4 = ((const float4*)&g_we[hp][q][0][0]) + g * 16; // c row: 2 f4
            float4 ea[8], eb[8];
            #pragma unroll
            for (int i = 0; i < 8; i++) { ea[i] = we4[i * 2]; eb[i] = we4[i * 2 + 1]; }

            const int h = 2 * by + hp;
            #pragma unroll
            for (int t = 0; t < 2; t++) {
                const int ml = l + t * 32;
                const int px = q * 64 + ml;
                float4 mA = make_float4(midf[0 * 128 + px], midf[1 * 128 + px],
                                        midf[2 * 128 + px], midf[3 * 128 + px]);
                float4 mB = make_float4(midf[4 * 128 + px], midf[5 * 128 + px],
                                        midf[6 * 128 + px], midf[7 * 128 + px]);
                const int w = 2 * (mbase + ml) + q;
                float* ob = out + ((size_t)(b * C_ + g * 8) * HHR_ + h) * WHR_ + w;
                #pragma unroll
                for (int i = 0; i < 8; i++) {
                    float a = fea[t][i]
                            + ea[i].x * mA.x + ea[i].y * mA.y + ea[i].z * mA.z + ea[i].w * mA.w
                            + eb[i].x * mB.x + eb[i].y * mB.y + eb[i].z * mB.z + eb[i].w * mB.w;
                    ob[(size_t)i * (HHR_ * WHR_)] = a;
                }
            }
        }
        __syncthreads();   // protect part[] before next hp phase reuses it
    }
}

// ---------------------------------------------------------------------------
extern "C" void kernel_launch(void* const* d_in, const int* in_sizes, int n_in,
                              void* d_out, int out_size)
{
    const float* fused = (const float*)d_in[1];
    const float* WC    = (const float*)d_in[2];
    const float* WE    = (const float*)d_in[3];
    const float* w1    = (const float*)d_in[4];
    const float* b1    = (const float*)d_in[5];
    const float* w2    = (const float*)d_in[6];
    const float* b2    = (const float*)d_in[7];
    const float* rw    = (const float*)d_in[8];
    const float* rb    = (const float*)d_in[9];
    const float* ow    = (const float*)d_in[10];
    const float* ob    = (const float*)d_in[11];
    float* out = (float*)d_out;

    cudaFuncSetAttribute(upsample_main,
                         cudaFuncAttributeMaxDynamicSharedMemorySize, SMEM_BYTES);

    precompute_kernel<<<1, 256>>>(w1, b1, w2, b2, rw, rb, ow, ob, WC, WE);

    dim3 grid(WHR_ / 128, HHR_ / 2, B_);
    upsample_main<<<grid, 512, SMEM_BYTES>>>(fused, out);
}

// round 5
// speedup vs baseline: 2.6246x; 2.6246x over previous
#include <cuda_runtime.h>
#include <cuda_bf16.h>
#include <math.h>

// Problem constants (fixed by the dataset)
#define B_   2
#define C_   64
#define E_   4
#define HLR_ 192
#define WLR_ 192
#define HHR_ 384
#define WHR_ 384
#define HWLR_ (HLR_*WLR_)
#define HWHR_ (HHR_*WHR_)

// Precomputed per-parity quantities (4 variants: hp*2+wp)
__device__ float g_wc[2][2][8][64];    // dynamic compress weights [hp][wp][j][c]
__device__ float g_we[2][2][64][8];    // dynamic expand weights   [hp][wp][c][j]
__device__ float g_offx[2][2], g_offy[2][2];   // raw offsets (fallback path)
__device__ int   g_fast[2];            // per-hp: fast window path valid
__device__ int   g_dyf[2];             // fast: shared y0 delta (relative to byy)
__device__ int   g_dxmin[2];           // fast: window base delta (relative to m)
__device__ int   g_ox[2][2];           // fast: per-q tap offset in window (0/1)
__device__ float g_wxf[2][2], g_wyf[2][2];     // fast: per-q fracs

// ---------------------------------------------------------------------------
// Kernel 0: 4 parity variants of the MLP, routing-mixed dynamic weights, and
// the shared-window sampling constants. 1 block, 256 threads.
// ---------------------------------------------------------------------------
__global__ void __launch_bounds__(256) precompute_kernel(
    const float* __restrict__ w1, const float* __restrict__ b1,
    const float* __restrict__ w2, const float* __restrict__ b2,
    const float* __restrict__ rw, const float* __restrict__ rb,
    const float* __restrict__ ow, const float* __restrict__ ob,
    const float* __restrict__ WC, const float* __restrict__ WE)
{
    __shared__ float s_emb[4][64];
    __shared__ float s_rt[4][4];
    __shared__ float s_off[4][2];

    int tid = threadIdx.x;
    int v = tid >> 6;        // variant 0..3 = hp*2+wp
    int o = tid & 63;        // output neuron
    int hp = v >> 1, wp = v & 1;

    float ch = (hp + 0.5f) * 0.5f; ch = ch - floorf(ch + 0.001f) - 0.5f;
    float cw = (wp + 0.5f) * 0.5f; cw = cw - floorf(cw + 0.001f) - 0.5f;
    float inp0 = 0.5f, inp1 = 0.5f, inp2 = ch, inp3 = cw;

    float acc = b2[o];
    #pragma unroll 8
    for (int k = 0; k < 64; k++) {
        float e1 = b1[k]
                 + w1[k*4+0]*inp0 + w1[k*4+1]*inp1
                 + w1[k*4+2]*inp2 + w1[k*4+3]*inp3;
        e1 = fmaxf(e1, 0.0f);
        acc += w2[o*64 + k] * e1;
    }
    acc = fmaxf(acc, 0.0f);
    s_emb[v][o] = acc;
    __syncthreads();

    if (o < E_) {
        float a = rb[o];
        for (int k = 0; k < 64; k++) a += rw[o*64 + k] * s_emb[v][k];
        s_rt[v][o] = 1.0f / (1.0f + expf(-a));
    }
    if (o >= 8 && o < 10) {
        int k = o - 8;
        float a = ob[k];
        for (int j = 0; j < 64; j++) a += ow[k*64 + j] * s_emb[v][j];
        s_off[v][k] = a;
    }
    __syncthreads();

    // derived shared-window constants: one thread per hp
    if (tid < 2) {
        int hpp = tid;
        float ox0 = s_off[hpp*2 + 0][0], oy0 = s_off[hpp*2 + 0][1];
        float ox1 = s_off[hpp*2 + 1][0], oy1 = s_off[hpp*2 + 1][1];
        g_offx[hpp][0] = ox0; g_offx[hpp][1] = ox1;
        g_offy[hpp][0] = oy0; g_offy[hpp][1] = oy1;

        // px(w=2m+q) = m + (q+0.5)*0.5 - 0.5 + offx ; py(h=2byy+hp) similar
        float tx0 = -0.25f + ox0;
        float tx1 =  0.25f + ox1;
        float tyb = (hpp + 0.5f) * 0.5f - 0.5f;
        float ty0 = tyb + oy0;
        float ty1 = tyb + oy1;
        float fx0 = floorf(tx0), fx1 = floorf(tx1);
        float fy0 = floorf(ty0), fy1 = floorf(ty1);
        int dx0 = (int)fx0, dx1 = (int)fx1;
        int dy0 = (int)fy0, dy1 = (int)fy1;

        int fast = (dy0 == dy1) && (abs(dx1 - dx0) <= 1);
        g_fast[hpp] = fast;
        int dmn = min(dx0, dx1);
        g_dyf[hpp]   = dy0;
        g_dxmin[hpp] = dmn;
        g_ox[hpp][0] = dx0 - dmn;
        g_ox[hpp][1] = dx1 - dmn;
        g_wxf[hpp][0] = tx0 - fx0;  g_wxf[hpp][1] = tx1 - fx1;
        g_wyf[hpp][0] = ty0 - fy0;  g_wyf[hpp][1] = ty1 - fy1;
    }

    // dynamic weights: 4 variants x 512 values each for wc and we
    float* gwc = &g_wc[0][0][0][0];
    float* gwe = &g_we[0][0][0][0];
    for (int idx = tid; idx < 4*512; idx += 256) {
        int vv = idx >> 9;
        int r  = idx & 511;
        float ac = 0.0f, ae = 0.0f;
        #pragma unroll
        for (int e = 0; e < E_; e++) {
            float rt = s_rt[vv][e];
            ac += rt * WC[e*512 + r];
            ae += rt * WE[e*512 + r];
        }
        gwc[vv*512 + r] = ac;
        gwe[vv*512 + r] = ae;
    }
}

// ---------------------------------------------------------------------------
// Main kernel. Block = 512 threads = 16 warps.
//   warp ww: g = ww & 7 (channel group of 8), half = ww >> 3.
//   lane l -> LR column m = mbase + half*32 + l; thread produces BOTH parities
//   (HR cols w=2m and 2m+1) so bilinear taps and weights are shared and the
//   stores are contiguous float2.
// grid = (WHR/128, HHR, B).
// ---------------------------------------------------------------------------
__global__ void __launch_bounds__(512) upsample_main(
    const float* __restrict__ fused, float* __restrict__ out)
{
    __shared__ float s_wc[2][8][64];        // [q][j][c]
    __shared__ float s_we[2][64][8];        // [q][c][j]
    __shared__ float s_part[8][8][2][64];   // [j][g][q][m]
    __shared__ float s_midf[8][2][64];      // [j][q][m]

    const int tid  = threadIdx.x;
    const int l    = tid & 31;
    const int ww   = tid >> 5;
    const int g    = ww & 7;
    const int half = ww >> 3;
    const int h    = blockIdx.y;
    const int hp   = h & 1;
    const int byy  = h >> 1;
    const int b    = blockIdx.z;
    const int mbase = blockIdx.x * 64;
    const int ml   = half * 32 + l;          // m within block tile [0,64)
    const int m    = mbase + ml;             // LR column

    // Stage dynamic weights: 512 float4 (wc 256 + we 256), one per thread.
    {
        const float4* srcc = (const float4*)&g_wc[hp][0][0][0];
        const float4* srce = (const float4*)&g_we[hp][0][0][0];
        float4* dc = (float4*)&s_wc[0][0][0];
        float4* de = (float4*)&s_we[0][0][0];
        if (tid < 256) dc[tid] = srcc[tid];
        else           de[tid - 256] = srce[tid - 256];
    }
    __syncthreads();

    const float* basep = fused + (size_t)(b * C_ + g * 8) * HWLR_;

    float fea[2][8];

    if (g_fast[hp]) {
        // ---- shared 2-row x 3-col window serving both parities ----------
        const int y0 = byy + g_dyf[hp];
        const int xg = m + g_dxmin[hp];
        const bool yv0 = (y0 >= 0) && (y0 < HLR_);
        const bool yv1 = (y0 + 1 >= 0) && (y0 + 1 < HLR_);
        const int yc0 = min(max(y0, 0), HLR_ - 1);
        const int yc1 = min(max(y0 + 1, 0), HLR_ - 1);
        const float wx0 = g_wxf[hp][0], wx1 = g_wxf[hp][1];
        const float wy0 = g_wyf[hp][0], wy1 = g_wyf[hp][1];
        const int o0 = g_ox[hp][0], o1 = g_ox[hp][1];

        bool xv[3]; int xc[3];
        #pragma unroll
        for (int k = 0; k < 3; k++) {
            int x = xg + k;
            xv[k] = (x >= 0) && (x < WLR_);
            xc[k] = min(max(x, 0), WLR_ - 1);
        }

        #pragma unroll
        for (int i = 0; i < 8; i++) {
            const float* pl = basep + (size_t)i * HWLR_;
            const float* r0 = pl + yc0 * WLR_;
            const float* r1 = pl + yc1 * WLR_;
            float u[3], vv[3];
            #pragma unroll
            for (int k = 0; k < 3; k++) {
                u[k]  = (yv0 && xv[k]) ? r0[xc[k]] : 0.0f;
                vv[k] = (yv1 && xv[k]) ? r1[xc[k]] : 0.0f;
            }
            // q = 0
            {
                float ua = o0 ? u[1] : u[0],  ub = o0 ? u[2] : u[1];
                float va = o0 ? vv[1] : vv[0], vb = o0 ? vv[2] : vv[1];
                float top = ua * (1.0f - wx0) + ub * wx0;
                float bot = va * (1.0f - wx0) + vb * wx0;
                fea[0][i] = top * (1.0f - wy0) + bot * wy0;
            }
            // q = 1
            {
                float ua = o1 ? u[1] : u[0],  ub = o1 ? u[2] : u[1];
                float va = o1 ? vv[1] : vv[0], vb = o1 ? vv[2] : vv[1];
                float top = ua * (1.0f - wx1) + ub * wx1;
                float bot = va * (1.0f - wx1) + vb * wx1;
                fea[1][i] = top * (1.0f - wy1) + bot * wy1;
            }
        }
    } else {
        // ---- generic fallback: independent 4-tap gather per parity -------
        #pragma unroll
        for (int q = 0; q < 2; q++) {
            float px = (float)m + (q + 0.5f) * 0.5f - 0.5f + g_offx[hp][q];
            float py = (float)byy + (hp + 0.5f) * 0.5f - 0.5f + g_offy[hp][q];
            float x0f = floorf(px), y0f = floorf(py);
            float wx = px - x0f, wy = py - y0f;
            int x0 = (int)x0f, y0 = (int)y0f;
            bool vx0 = (x0 >= 0) && (x0 < WLR_);
            bool vx1 = (x0 + 1 >= 0) && (x0 + 1 < WLR_);
            bool vy0 = (y0 >= 0) && (y0 < HLR_);
            bool vy1 = (y0 + 1 >= 0) && (y0 + 1 < HLR_);
            float w00 = (vy0 && vx0) ? (1.0f - wx) * (1.0f - wy) : 0.0f;
            float w01 = (vy0 && vx1) ? wx * (1.0f - wy)          : 0.0f;
            float w10 = (vy1 && vx0) ? (1.0f - wx) * wy          : 0.0f;
            float w11 = (vy1 && vx1) ? wx * wy                   : 0.0f;
            int xc0 = min(max(x0, 0), WLR_ - 1);
            int xc1 = min(max(x0 + 1, 0), WLR_ - 1);
            int yc0 = min(max(y0, 0), HLR_ - 1);
            int yc1 = min(max(y0 + 1, 0), HLR_ - 1);
            #pragma unroll
            for (int i = 0; i < 8; i++) {
                const float* pl = basep + (size_t)i * HWLR_;
                const float* r0 = pl + yc0 * WLR_;
                const float* r1 = pl + yc1 * WLR_;
                fea[q][i] = r0[xc0] * w00 + r0[xc1] * w01
                          + r1[xc0] * w10 + r1[xc1] * w11;
            }
        }
    }

    // ---- Compress (8x8 matvec) for both parities ------------------------
    #pragma unroll
    for (int q = 0; q < 2; q++) {
        const float4* wc4 = (const float4*)&s_wc[q][0][g * 8];  // row stride 16 f4
        float4 fa = make_float4(fea[q][0], fea[q][1], fea[q][2], fea[q][3]);
        float4 fb = make_float4(fea[q][4], fea[q][5], fea[q][6], fea[q][7]);
        #pragma unroll
        for (int j = 0; j < 8; j++) {
            float4 wa = wc4[j * 16];
            float4 wb = wc4[j * 16 + 1];
            float a = wa.x * fa.x + wa.y * fa.y + wa.z * fa.z + wa.w * fa.w
                    + wb.x * fb.x + wb.y * fb.y + wb.z * fb.z + wb.w * fb.w;
            s_part[j][g][q][ml] = a;
        }
    }
    __syncthreads();

    // ---- Reduce partials over channel groups: 16 warps <-> (j,q) --------
    {
        const int j = ww >> 1, qq = ww & 1;
        float s0 = 0.0f, s1 = 0.0f;
        #pragma unroll
        for (int gg = 0; gg < 8; gg++) {
            s0 += s_part[j][gg][qq][l];
            s1 += s_part[j][gg][qq][l + 32];
        }
        s_midf[j][qq][l]      = s0;
        s_midf[j][qq][l + 32] = s1;
    }
    __syncthreads();

    // ---- Expand + residual + contiguous float2 stores -------------------
    float mid0[8], mid1[8];
    #pragma unroll
    for (int j = 0; j < 8; j++) {
        mid0[j] = s_midf[j][0][ml];
        mid1[j] = s_midf[j][1][ml];
    }
    float* ob = out + ((size_t)(b * C_ + g * 8) * HHR_ + h) * WHR_ + 2 * m;
    #pragma unroll
    for (int i = 0; i < 8; i++) {
        const float4* we0 = (const float4*)&s_we[0][g * 8 + i][0];
        const float4* we1 = (const float4*)&s_we[1][g * 8 + i][0];
        float4 ea0 = we0[0], eb0 = we0[1];
        float4 ea1 = we1[0], eb1 = we1[1];
        float r0 = fea[0][i]
                 + ea0.x * mid0[0] + ea0.y * mid0[1] + ea0.z * mid0[2] + ea0.w * mid0[3]
                 + eb0.x * mid0[4] + eb0.y * mid0[5] + eb0.z * mid0[6] + eb0.w * mid0[7];
        float r1 = fea[1][i]
                 + ea1.x * mid1[0] + ea1.y * mid1[1] + ea1.z * mid1[2] + ea1.w * mid1[3]
                 + eb1.x * mid1[4] + eb1.y * mid1[5] + eb1.z * mid1[6] + eb1.w * mid1[7];
        float2 rv = make_float2(r0, r1);
        *(float2*)(ob + (size_t)i * HWHR_) = rv;
    }
}

// ---------------------------------------------------------------------------
extern "C" void kernel_launch(void* const* d_in, const int* in_sizes, int n_in,
                              void* d_out, int out_size)
{
    const float* fused = (const float*)d_in[1];
    const float* WC    = (const float*)d_in[2];
    const float* WE    = (const float*)d_in[3];
    const float* w1    = (const float*)d_in[4];
    const float* b1    = (const float*)d_in[5];
    const float* w2    = (const float*)d_in[6];
    const float* b2    = (const float*)d_in[7];
    const float* rw    = (const float*)d_in[8];
    const float* rb    = (const float*)d_in[9];
    const float* ow    = (const float*)d_in[10];
    const float* ob    = (const float*)d_in[11];
    float* out = (float*)d_out;

    precompute_kernel<<<1, 256>>>(w1, b1, w2, b2, rw, rb, ow, ob, WC, WE);

    dim3 grid(WHR_ / 128, HHR_, B_);
    upsample_main<<<grid, 512>>>(fused, out);
}